// round 14
// baseline (speedup 1.0000x reference)
#include <cuda_runtime.h>
#include <cuda_fp16.h>
#include <math.h>
#include <stdint.h>

constexpr int BATCH  = 4;
constexpr int SEQ    = 2048;
constexpr int DMODEL = 512;
constexpr int NH     = 8;
constexpr int HD     = 64;
constexpr int FFI    = 2048;
constexpr int MROWS  = BATCH * SEQ;   // 8192
constexpr int BH     = BATCH * NH;    // 32

// ---------------- baseline-PTX helpers ----------------
__device__ __forceinline__ uint32_t smem_u32(const void* p) {
    uint32_t a;
    asm("{ .reg .u64 t; cvta.to.shared.u64 t, %1; cvt.u32.u64 %0, t; }" : "=r"(a) : "l"(p));
    return a;
}
#define CP_ASYNC16(dst, src) \
    asm volatile("cp.async.cg.shared.global [%0], [%1], 16;" :: "r"(dst), "l"(src))
#define CP_COMMIT() asm volatile("cp.async.commit_group;" ::: "memory")
#define CP_WAIT(n)  asm volatile("cp.async.wait_group %0;" :: "n"(n) : "memory")
#define LDSM4(r0, r1, r2, r3, addr) \
    asm volatile("ldmatrix.sync.aligned.m8n8.x4.shared.b16 {%0,%1,%2,%3}, [%4];" \
        : "=r"(r0), "=r"(r1), "=r"(r2), "=r"(r3) : "r"(addr))
#define LDSM4T(r0, r1, r2, r3, addr) \
    asm volatile("ldmatrix.sync.aligned.m8n8.x4.trans.shared.b16 {%0,%1,%2,%3}, [%4];" \
        : "=r"(r0), "=r"(r1), "=r"(r2), "=r"(r3) : "r"(addr))
#define MMA16816(c, a, b0, b1) \
    asm volatile("mma.sync.aligned.m16n8k16.row.col.f32.f16.f16.f32 " \
        "{%0,%1,%2,%3}, {%4,%5,%6,%7}, {%8,%9}, {%0,%1,%2,%3};" \
        : "+f"((c)[0]), "+f"((c)[1]), "+f"((c)[2]), "+f"((c)[3]) \
        : "r"((a)[0]), "r"((a)[1]), "r"((a)[2]), "r"((a)[3]), "r"(b0), "r"(b1))

__device__ __forceinline__ void split2h(float v, __half& h, __half& l) {
    h = __float2half_rn(v);
    l = __float2half_rn(v - __half2float(h));
}
__device__ __forceinline__ uint32_t pack_h(float x, float y) {
    union { __half2 h2; uint32_t u; } r;
    r.h2 = __halves2half2(__float2half_rn(x), __float2half_rn(y));
    return r.u;
}
__device__ __forceinline__ void pack_hl(float x, float y, uint32_t& hi, uint32_t& lo) {
    __half hx, lx, hy, ly;
    split2h(x, hx, lx);
    split2h(y, hy, ly);
    union { __half2 h2; uint32_t u; } a, b;
    a.h2 = __halves2half2(hx, hy);
    b.h2 = __halves2half2(lx, ly);
    hi = a.u; lo = b.u;
}

// ---------------- device scratch ----------------
// QKV: 3-term A'=[hi|lo|hi], B'=[hi|hi|lo]
// Wo:  2-term A'=att pair (exact), B'=[Wo|Wo] dup
// FFN1: 2-term A'=out pair (exact), B'=[W1|W1] dup -> h single fp16
// FFN2: plain  A=h single, B=W2^T single
#define AL __align__(16)
__device__ AL __half g_xp[MROWS * 3 * DMODEL];            // x'    [8192,1536]
__device__ AL __half g_qkvWp[1536 * 3 * DMODEL];          // B'qkv [1536,1536]
__device__ AL __half g_WoTp[DMODEL * 2 * DMODEL];         // B'Wo  [512,1024] dup
__device__ AL __half g_W1Tp[FFI * 2 * DMODEL];            // B'W1  [2048,1024] dup
__device__ AL __half g_W2Tp[DMODEL * FFI];                // W2^T  [512,2048] single
__device__ AL __half g_qhi[BH * SEQ * HD], g_qlo[BH * SEQ * HD];
__device__ AL __half g_khi[BH * SEQ * HD], g_klo[BH * SEQ * HD];
__device__ AL __half g_vhi[BH * SEQ * HD], g_vlo[BH * SEQ * HD];
__device__ AL __half g_attp[MROWS * 2 * DMODEL];          // att'  [8192,1024] pair
__device__ AL __half g_outp[MROWS * 2 * DMODEL];          // out'  [8192,1024] pair
__device__ AL __half g_h16[MROWS * FFI];                  // h     [8192,2048] single

// ---------------- prep kernels ----------------
__global__ void split3_rows(const float* __restrict__ in, __half* __restrict__ out,
                            int M, int K) {
    int i = blockIdx.x * 256 + threadIdx.x;
    if (i >= M * K) return;
    int m = i / K, k = i - m * K;
    __half h, l; split2h(in[i], h, l);
    size_t base = (size_t)m * 3 * K;
    out[base + k] = h; out[base + K + k] = l; out[base + 2 * K + k] = h;
}
__global__ void transpose_dup2(const float* __restrict__ W, __half* __restrict__ out,
                               int Kd, int Nd) {
    int i = blockIdx.x * 256 + threadIdx.x;
    if (i >= Nd * Kd) return;
    int n = i / Kd, k = i - n * Kd;
    __half h = __float2half_rn(W[(size_t)k * Nd + n]);
    size_t base = (size_t)n * 2 * Kd;
    out[base + k] = h; out[base + Kd + k] = h;
}
__global__ void transpose_single(const float* __restrict__ W, __half* __restrict__ out,
                                 int Kd, int Nd) {
    int i = blockIdx.x * 256 + threadIdx.x;
    if (i >= Nd * Kd) return;
    int n = i / Kd, k = i - n * Kd;
    out[(size_t)n * Kd + k] = __float2half_rn(W[(size_t)k * Nd + n]);
}
__global__ void prep_qkvW(const float* __restrict__ Wq, const float* __restrict__ Wk,
                          const float* __restrict__ Wv) {
    int i = blockIdx.x * 256 + threadIdx.x;
    if (i >= 1536 * DMODEL) return;
    int n = i >> 9, k = i & 511;
    int which = n >> 9, h = (n >> 6) & 7, kk = n & 63;
    const float* W = which == 0 ? Wq : which == 1 ? Wk : Wv;
    __half hh, ll; split2h(W[((size_t)h * DMODEL + k) * HD + kk], hh, ll);
    size_t base = (size_t)n * 1536;
    g_qkvWp[base + k] = hh; g_qkvWp[base + 512 + k] = hh; g_qkvWp[base + 1024 + k] = ll;
}

// ---------------- fp16 K-concat GEMM (proven core) -------------------------
// EPI: 0 = QKV scatter fp16 hi/lo; 1 = pair-store [hi|lo];
//      2 = bias+relu+SINGLE-fp16 store; 3 = bias + fp32 out
constexpr int STAGE_B = 32768;
constexpr int GEMM_SMEM = 3 * STAGE_B;   // 96 KB

template <int EPI>
__global__ __launch_bounds__(256, 2)
void mma_gemm(const __half* __restrict__ A, const __half* __restrict__ B,
              const float* __restrict__ bias, float* __restrict__ outF,
              __half* __restrict__ outB, int N, int Kp) {
    extern __shared__ char smdyn[];
    const uint32_t sb = smem_u32(smdyn);
    const int tid = threadIdx.x, lane = tid & 31, wid = tid >> 5;
    const int wm = wid & 3, wn = wid >> 2;
    const int rowBase = blockIdx.y * 128, colBase = blockIdx.x * 128;
    const int chunks = Kp >> 6;

    float C[2][8][4];
#pragma unroll
    for (int a = 0; a < 2; a++)
#pragma unroll
        for (int b = 0; b < 8; b++)
#pragma unroll
            for (int c = 0; c < 4; c++) C[a][b][c] = 0.f;

    auto issue = [&](int cchunk) {
        int s = cchunk % 3;
        uint32_t stA = sb + s * STAGE_B, stB = stA + 16384;
        const char* Ag = (const char*)(A + (size_t)rowBase * Kp + cchunk * 64);
        const char* Bg = (const char*)(B + (size_t)colBase * Kp + cchunk * 64);
#pragma unroll
        for (int i = 0; i < 4; i++) {
            int id = tid + i * 256;
            int r = id >> 3, ch = id & 7;
            uint32_t off = (uint32_t)(r * 8 + (ch ^ (r & 7))) * 16;
            CP_ASYNC16(stA + off, Ag + (size_t)r * Kp * 2 + ch * 16);
            CP_ASYNC16(stB + off, Bg + (size_t)r * Kp * 2 + ch * 16);
        }
        CP_COMMIT();
    };

    issue(0);
    if (chunks > 1) issue(1);

    const int laneA_row = lane & 15;
    const int laneA_ks  = lane >> 4;
    const int laneB_row = (lane & 7) + ((lane >> 4) << 3);
    const int laneB_ks  = (lane >> 3) & 1;

    for (int c = 0; c < chunks; c++) {
        CP_WAIT(1);
        __syncthreads();
        if (c + 2 < chunks) issue(c + 2);

        uint32_t stA = sb + (c % 3) * STAGE_B, stB = stA + 16384;

#pragma unroll
        for (int ks = 0; ks < 4; ks++) {
            uint32_t a[2][4];
#pragma unroll
            for (int mt = 0; mt < 2; mt++) {
                int rowA = wm * 32 + mt * 16 + laneA_row;
                int chA = ks * 2 + laneA_ks;
                uint32_t ad = stA + (uint32_t)(rowA * 8 + (chA ^ (rowA & 7))) * 16;
                LDSM4(a[mt][0], a[mt][1], a[mt][2], a[mt][3], ad);
            }
#pragma unroll
            for (int np = 0; np < 4; np++) {
                int rowB = wn * 64 + np * 16 + laneB_row;
                int chB = ks * 2 + laneB_ks;
                uint32_t bd = stB + (uint32_t)(rowB * 8 + (chB ^ (rowB & 7))) * 16;
                uint32_t b0, b1, b2, b3;
                LDSM4(b0, b1, b2, b3, bd);
#pragma unroll
                for (int mt = 0; mt < 2; mt++) {
                    MMA16816(C[mt][np * 2 + 0], a[mt], b0, b1);
                    MMA16816(C[mt][np * 2 + 1], a[mt], b2, b3);
                }
            }
        }
    }

#pragma unroll
    for (int mt = 0; mt < 2; mt++) {
#pragma unroll
        for (int half = 0; half < 2; half++) {
            int m = rowBase + wm * 32 + mt * 16 + (lane >> 2) + half * 8;
#pragma unroll
            for (int nt = 0; nt < 8; nt++) {
                int n = colBase + wn * 64 + nt * 8 + (lane & 3) * 2;
                float v0 = C[mt][nt][half * 2 + 0];
                float v1 = C[mt][nt][half * 2 + 1];
                if (EPI == 0) {
                    int b = m >> 11, t = m & 2047;
                    int which = n >> 9, h = (n >> 6) & 7, kk = n & 63;
                    __half* dh = which == 0 ? g_qhi : which == 1 ? g_khi : g_vhi;
                    __half* dl = which == 0 ? g_qlo : which == 1 ? g_klo : g_vlo;
                    uint32_t hi, lo;
                    pack_hl(v0, v1, hi, lo);
                    size_t idx = ((size_t)((b * NH + h) * SEQ + t)) * HD + kk;
                    *(uint32_t*)&dh[idx] = hi;
                    *(uint32_t*)&dl[idx] = lo;
                } else if (EPI == 3) {
                    *(float2*)&outF[(size_t)m * N + n] =
                        make_float2(v0 + bias[n], v1 + bias[n + 1]);
                } else if (EPI == 2) {
                    v0 = fmaxf(v0 + bias[n], 0.f);
                    v1 = fmaxf(v1 + bias[n + 1], 0.f);
                    *(uint32_t*)&outB[(size_t)m * N + n] = pack_h(v0, v1);
                } else {
                    uint32_t hi, lo;
                    pack_hl(v0, v1, hi, lo);
                    size_t base = (size_t)m * (2 * N) + n;
                    *(uint32_t*)&outB[base]     = hi;
                    *(uint32_t*)&outB[base + N] = lo;
                }
            }
        }
    }
}

// ---------------- flash attention: S 3-term, PV P-single (O = Ph·V) --------
constexpr int F_STAGE = 32768;
constexpr int FLASH_SMEM = 32768 + 2 * F_STAGE;   // 96 KB

__global__ __launch_bounds__(256, 1)
void flash_mma() {
    extern __shared__ char smdyn[];
    const uint32_t sb = smem_u32(smdyn);
    const int tid = threadIdx.x, lane = tid & 31, wid = tid >> 5;
    const int bh = blockIdx.y;
    const int b = bh >> 3, h = bh & 7;
    const int q0 = blockIdx.x * 128;

    const uint32_t sQh = sb, sQl = sb + 16384;
    const size_t bhBase = (size_t)bh * SEQ * HD;

    auto issue_kv = [&](int t) {
        int s = t & 1;
        uint32_t st = sb + 32768 + s * F_STAGE;
        int key0 = t * 64;
        const __half* srcs[4] = { g_khi, g_klo, g_vhi, g_vlo };
#pragma unroll
        for (int arr = 0; arr < 4; arr++) {
            uint32_t base = st + arr * 8192;
            const char* g = (const char*)(srcs[arr] + bhBase + (size_t)key0 * HD);
#pragma unroll
            for (int i = 0; i < 2; i++) {
                int id = tid + i * 256;
                int r = id >> 3, ch = id & 7;
                uint32_t off = (uint32_t)(r * 8 + (ch ^ (r & 7))) * 16;
                CP_ASYNC16(base + off, g + (size_t)r * 128 + ch * 16);
            }
        }
        CP_COMMIT();
    };

    issue_kv(0);
    issue_kv(1);

#pragma unroll
    for (int i = 0; i < 4; i++) {
        int id = tid + i * 256;
        int r = id >> 3, ch = id & 7;
        uint32_t off = (uint32_t)(r * 8 + (ch ^ (r & 7))) * 16;
        size_t gidx = bhBase + (size_t)(q0 + r) * HD + ch * 8;
        *(float4*)(smdyn + (sQh - sb) + off) = *(const float4*)&g_qhi[gidx];
        *(float4*)(smdyn + (sQl - sb) + off) = *(const float4*)&g_qlo[gidx];
    }
    __syncthreads();

    const int laneA_row = lane & 15;
    const int laneA_ks  = lane >> 4;
    const int laneB_row = (lane & 7) + ((lane >> 4) << 3);
    const int laneB_ks  = (lane >> 3) & 1;
    const int t4 = lane >> 3, rr = lane & 7;

    uint32_t qh[4][4], ql[4][4];
#pragma unroll
    for (int ks = 0; ks < 4; ks++) {
        int rowA = wid * 16 + laneA_row;
        int chA = ks * 2 + laneA_ks;
        uint32_t sw = (uint32_t)(rowA * 8 + (chA ^ (rowA & 7))) * 16;
        LDSM4(qh[ks][0], qh[ks][1], qh[ks][2], qh[ks][3], sQh + sw);
        LDSM4(ql[ks][0], ql[ks][1], ql[ks][2], ql[ks][3], sQl + sw);
    }

    float o[8][4];
#pragma unroll
    for (int nt = 0; nt < 8; nt++)
#pragma unroll
        for (int j = 0; j < 4; j++) o[nt][j] = 0.f;
    float m0 = -1e30f, m1 = -1e30f, l0 = 0.f, l1 = 0.f;

    constexpr int NT = SEQ / 64;
    for (int kt = 0; kt < NT; kt++) {
        if (kt < NT - 1) { CP_WAIT(1); } else { CP_WAIT(0); }
        __syncthreads();

        uint32_t st = sb + 32768 + (kt & 1) * F_STAGE;
        uint32_t sKh = st, sKl = st + 8192, sVh = st + 16384, sVl = st + 24576;

        float c[8][4];
#pragma unroll
        for (int nt = 0; nt < 8; nt++)
#pragma unroll
            for (int j = 0; j < 4; j++) c[nt][j] = 0.f;

#pragma unroll
        for (int ks = 0; ks < 4; ks++) {
#pragma unroll
            for (int np = 0; np < 4; np++) {
                int rowB = np * 16 + laneB_row;
                int chB = ks * 2 + laneB_ks;
                uint32_t sw = (uint32_t)(rowB * 8 + (chB ^ (rowB & 7))) * 16;
                uint32_t kh0, kh1, kh2, kh3, kl0, kl1, kl2, kl3;
                LDSM4(kh0, kh1, kh2, kh3, sKh + sw);
                LDSM4(kl0, kl1, kl2, kl3, sKl + sw);
                MMA16816(c[np * 2 + 0], qh[ks], kh0, kh1);
                MMA16816(c[np * 2 + 0], ql[ks], kh0, kh1);
                MMA16816(c[np * 2 + 0], qh[ks], kl0, kl1);
                MMA16816(c[np * 2 + 1], qh[ks], kh2, kh3);
                MMA16816(c[np * 2 + 1], ql[ks], kh2, kh3);
                MMA16816(c[np * 2 + 1], qh[ks], kl2, kl3);
            }
        }

        float mx0 = -1e30f, mx1 = -1e30f;
#pragma unroll
        for (int nt = 0; nt < 8; nt++) {
            c[nt][0] *= 0.125f; c[nt][1] *= 0.125f;
            c[nt][2] *= 0.125f; c[nt][3] *= 0.125f;
            mx0 = fmaxf(mx0, fmaxf(c[nt][0], c[nt][1]));
            mx1 = fmaxf(mx1, fmaxf(c[nt][2], c[nt][3]));
        }
        mx0 = fmaxf(mx0, __shfl_xor_sync(0xffffffffu, mx0, 1));
        mx0 = fmaxf(mx0, __shfl_xor_sync(0xffffffffu, mx0, 2));
        mx1 = fmaxf(mx1, __shfl_xor_sync(0xffffffffu, mx1, 1));
        mx1 = fmaxf(mx1, __shfl_xor_sync(0xffffffffu, mx1, 2));

        float mn0 = fmaxf(m0, mx0), mn1 = fmaxf(m1, mx1);
        float a0 = __expf(m0 - mn0), a1 = __expf(m1 - mn1);
        m0 = mn0; m1 = mn1;

        float s0 = 0.f, s1 = 0.f;
#pragma unroll
        for (int nt = 0; nt < 8; nt++) {
            c[nt][0] = __expf(c[nt][0] - m0);
            c[nt][1] = __expf(c[nt][1] - m0);
            c[nt][2] = __expf(c[nt][2] - m1);
            c[nt][3] = __expf(c[nt][3] - m1);
            s0 += c[nt][0] + c[nt][1];
            s1 += c[nt][2] + c[nt][3];
        }
        s0 += __shfl_xor_sync(0xffffffffu, s0, 1);
        s0 += __shfl_xor_sync(0xffffffffu, s0, 2);
        s1 += __shfl_xor_sync(0xffffffffu, s1, 1);
        s1 += __shfl_xor_sync(0xffffffffu, s1, 2);
        l0 = l0 * a0 + s0;
        l1 = l1 * a1 + s1;

#pragma unroll
        for (int nt = 0; nt < 8; nt++) {
            o[nt][0] *= a0; o[nt][1] *= a0;
            o[nt][2] *= a1; o[nt][3] *= a1;
        }

        // P -> single fp16 A-fragments
        uint32_t ph[4][4];
#pragma unroll
        for (int pk = 0; pk < 4; pk++) {
            int n0i = pk * 2, n1i = pk * 2 + 1;
            ph[pk][0] = pack_h(c[n0i][0], c[n0i][1]);
            ph[pk][1] = pack_h(c[n0i][2], c[n0i][3]);
            ph[pk][2] = pack_h(c[n1i][0], c[n1i][1]);
            ph[pk][3] = pack_h(c[n1i][2], c[n1i][3]);
        }

        // O += Ph·Vh + Ph·Vl   (exact in V; only P rounding)
#pragma unroll
        for (int pk = 0; pk < 4; pk++) {
#pragma unroll
            for (int np = 0; np < 4; np++) {
                int rowV = pk * 16 + (t4 & 1) * 8 + rr;
                int chV = np * 2 + (t4 >> 1);
                uint32_t sw = (uint32_t)(rowV * 8 + (chV ^ (rowV & 7))) * 16;
                uint32_t vh0, vh1, vh2, vh3, vl0, vl1, vl2, vl3;
                LDSM4T(vh0, vh1, vh2, vh3, sVh + sw);
                LDSM4T(vl0, vl1, vl2, vl3, sVl + sw);
                MMA16816(o[np * 2 + 0], ph[pk], vh0, vh1);
                MMA16816(o[np * 2 + 0], ph[pk], vl0, vl1);
                MMA16816(o[np * 2 + 1], ph[pk], vh2, vh3);
                MMA16816(o[np * 2 + 1], ph[pk], vl2, vl3);
            }
        }

        __syncthreads();
        if (kt + 2 < NT) issue_kv(kt + 2);
    }

    // epilogue: att' PAIR [hi|lo], raw-reshape rows of length 1024
    float inv0 = 1.f / l0, inv1 = 1.f / l1;
#pragma unroll
    for (int half = 0; half < 2; half++) {
        int t = q0 + wid * 16 + (lane >> 2) + half * 8;
        float inv = half ? inv1 : inv0;
        size_t row2 = (size_t)b * SEQ + h * 256 + (t >> 3);
        size_t rb = row2 * 1024 + (t & 7) * 64;
#pragma unroll
        for (int nt = 0; nt < 8; nt++) {
            int col = nt * 8 + (lane & 3) * 2;
            float v0 = o[nt][half * 2 + 0] * inv;
            float v1 = o[nt][half * 2 + 1] * inv;
            uint32_t hi, lo;
            pack_hl(v0, v1, hi, lo);
            *(uint32_t*)&g_attp[rb + col]       = hi;
            *(uint32_t*)&g_attp[rb + 512 + col] = lo;
        }
    }
}

// ---------------- launch ----------------
extern "C" void kernel_launch(void* const* d_in, const int* in_sizes, int n_in,
                              void* d_out, int out_size) {
    const float* x  = (const float*)d_in[0];
    const float* Wq = (const float*)d_in[1];
    const float* Wk = (const float*)d_in[2];
    const float* Wv = (const float*)d_in[3];
    const float* Wo = (const float*)d_in[4];
    const float* W1 = (const float*)d_in[5];
    const float* b1 = (const float*)d_in[6];
    const float* W2 = (const float*)d_in[7];
    const float* b2 = (const float*)d_in[8];
    float* y = (float*)d_out;

    void *xp, *qwp, *wop, *w1p, *w2p, *atp, *outp, *hp;
    cudaGetSymbolAddress(&xp,  g_xp);
    cudaGetSymbolAddress(&qwp, g_qkvWp);
    cudaGetSymbolAddress(&wop, g_WoTp);
    cudaGetSymbolAddress(&w1p, g_W1Tp);
    cudaGetSymbolAddress(&w2p, g_W2Tp);
    cudaGetSymbolAddress(&atp, g_attp);
    cudaGetSymbolAddress(&outp, g_outp);
    cudaGetSymbolAddress(&hp,  g_h16);

    cudaFuncSetAttribute(mma_gemm<0>, cudaFuncAttributeMaxDynamicSharedMemorySize, GEMM_SMEM);
    cudaFuncSetAttribute(mma_gemm<1>, cudaFuncAttributeMaxDynamicSharedMemorySize, GEMM_SMEM);
    cudaFuncSetAttribute(mma_gemm<2>, cudaFuncAttributeMaxDynamicSharedMemorySize, GEMM_SMEM);
    cudaFuncSetAttribute(mma_gemm<3>, cudaFuncAttributeMaxDynamicSharedMemorySize, GEMM_SMEM);
    cudaFuncSetAttribute(flash_mma, cudaFuncAttributeMaxDynamicSharedMemorySize, FLASH_SMEM);

    // prep
    split3_rows<<<(MROWS * DMODEL + 255) / 256, 256>>>(x, (__half*)xp, MROWS, DMODEL);
    prep_qkvW<<<(1536 * DMODEL + 255) / 256, 256>>>(Wq, Wk, Wv);
    transpose_dup2<<<(DMODEL * DMODEL + 255) / 256, 256>>>(Wo, (__half*)wop, DMODEL, DMODEL);
    transpose_dup2<<<(DMODEL * FFI + 255) / 256, 256>>>(W1, (__half*)w1p, DMODEL, FFI);
    transpose_single<<<(FFI * DMODEL + 255) / 256, 256>>>(W2, (__half*)w2p, FFI, DMODEL);

    // 1. QKV (3-term, Kp=1536) -> q/k/v fp16 hi/lo
    mma_gemm<0><<<dim3(12, 64), 256, GEMM_SMEM>>>(
        (const __half*)xp, (const __half*)qwp, nullptr, nullptr, nullptr, 1536, 1536);

    // 2. flash attention (P-single PV) -> att' pair [hi|lo]
    flash_mma<<<dim3(SEQ / 128, BH), 256, FLASH_SMEM>>>();

    // 3. Wo (2-term, Kp=1024) -> out' pair [hi|lo]
    mma_gemm<1><<<dim3(4, 64), 256, GEMM_SMEM>>>(
        (const __half*)atp, (const __half*)wop, nullptr, nullptr,
        (__half*)outp, DMODEL, 1024);

    // 4. FFN1 (2-term, Kp=1024, bias+relu) -> h single fp16
    mma_gemm<2><<<dim3(16, 64), 256, GEMM_SMEM>>>(
        (const __half*)outp, (const __half*)w1p, b1, nullptr,
        (__half*)hp, FFI, 1024);

    // 5. FFN2 (plain, Kp=2048, bias) -> y fp32
    mma_gemm<3><<<dim3(4, 64), 256, GEMM_SMEM>>>(
        (const __half*)hp, (const __half*)w2p, b2, y, nullptr, DMODEL, 2048);
}

// round 15
// speedup vs baseline: 1.6559x; 1.6559x over previous
#include <cuda_runtime.h>
#include <cuda_fp16.h>
#include <math.h>
#include <stdint.h>

constexpr int BATCH  = 4;
constexpr int SEQ    = 2048;
constexpr int DMODEL = 512;
constexpr int NH     = 8;
constexpr int HD     = 64;
constexpr int FFI    = 2048;
constexpr int MROWS  = BATCH * SEQ;   // 8192
constexpr int BH     = BATCH * NH;    // 32

// ---------------- baseline-PTX helpers ----------------
__device__ __forceinline__ uint32_t smem_u32(const void* p) {
    uint32_t a;
    asm("{ .reg .u64 t; cvta.to.shared.u64 t, %1; cvt.u32.u64 %0, t; }" : "=r"(a) : "l"(p));
    return a;
}
#define CP_ASYNC16(dst, src) \
    asm volatile("cp.async.cg.shared.global [%0], [%1], 16;" :: "r"(dst), "l"(src))
#define CP_COMMIT() asm volatile("cp.async.commit_group;" ::: "memory")
#define CP_WAIT(n)  asm volatile("cp.async.wait_group %0;" :: "n"(n) : "memory")
#define LDSM4(r0, r1, r2, r3, addr) \
    asm volatile("ldmatrix.sync.aligned.m8n8.x4.shared.b16 {%0,%1,%2,%3}, [%4];" \
        : "=r"(r0), "=r"(r1), "=r"(r2), "=r"(r3) : "r"(addr))
#define LDSM4T(r0, r1, r2, r3, addr) \
    asm volatile("ldmatrix.sync.aligned.m8n8.x4.trans.shared.b16 {%0,%1,%2,%3}, [%4];" \
        : "=r"(r0), "=r"(r1), "=r"(r2), "=r"(r3) : "r"(addr))
#define MMA16816(c, a, b0, b1) \
    asm volatile("mma.sync.aligned.m16n8k16.row.col.f32.f16.f16.f32 " \
        "{%0,%1,%2,%3}, {%4,%5,%6,%7}, {%8,%9}, {%0,%1,%2,%3};" \
        : "+f"((c)[0]), "+f"((c)[1]), "+f"((c)[2]), "+f"((c)[3]) \
        : "r"((a)[0]), "r"((a)[1]), "r"((a)[2]), "r"((a)[3]), "r"(b0), "r"(b1))

__device__ __forceinline__ void split2h(float v, __half& h, __half& l) {
    h = __float2half_rn(v);
    l = __float2half_rn(v - __half2float(h));
}
__device__ __forceinline__ uint32_t pack_h(float x, float y) {
    union { __half2 h2; uint32_t u; } r;
    r.h2 = __halves2half2(__float2half_rn(x), __float2half_rn(y));
    return r.u;
}
__device__ __forceinline__ void pack_hl(float x, float y, uint32_t& hi, uint32_t& lo) {
    __half hx, lx, hy, ly;
    split2h(x, hx, lx);
    split2h(y, hy, ly);
    union { __half2 h2; uint32_t u; } a, b;
    a.h2 = __halves2half2(hx, hy);
    b.h2 = __halves2half2(lx, ly);
    hi = a.u; lo = b.u;
}

// ---------------- device scratch ----------------
// QKV: 3-term A'=[hi|lo|hi], B'=[hi|hi|lo]; q/k hi+lo, v SINGLE fp16
// Wo:  2-term A'=att pair (exact), B'=[Wo|Wo] dup
// FFN1: 2-term A'=out pair (exact), B'=[W1|W1] dup -> h single fp16
// FFN2: plain  A=h single, B=W2^T single
#define AL __align__(16)
__device__ AL __half g_xp[MROWS * 3 * DMODEL];            // x'    [8192,1536]
__device__ AL __half g_qkvWp[1536 * 3 * DMODEL];          // B'qkv [1536,1536]
__device__ AL __half g_WoTp[DMODEL * 2 * DMODEL];         // B'Wo  [512,1024] dup
__device__ AL __half g_W1Tp[FFI * 2 * DMODEL];            // B'W1  [2048,1024] dup
__device__ AL __half g_W2Tp[DMODEL * FFI];                // W2^T  [512,2048] single
__device__ AL __half g_qhi[BH * SEQ * HD], g_qlo[BH * SEQ * HD];
__device__ AL __half g_khi[BH * SEQ * HD], g_klo[BH * SEQ * HD];
__device__ AL __half g_vhi[BH * SEQ * HD];                // v single
__device__ AL __half g_attp[MROWS * 2 * DMODEL];          // att'  [8192,1024] pair
__device__ AL __half g_outp[MROWS * 2 * DMODEL];          // out'  [8192,1024] pair
__device__ AL __half g_h16[MROWS * FFI];                  // h     [8192,2048] single

// ---------------- prep kernels ----------------
__global__ void split3_rows(const float* __restrict__ in, __half* __restrict__ out,
                            int M, int K) {
    int i = blockIdx.x * 256 + threadIdx.x;
    if (i >= M * K) return;
    int m = i / K, k = i - m * K;
    __half h, l; split2h(in[i], h, l);
    size_t base = (size_t)m * 3 * K;
    out[base + k] = h; out[base + K + k] = l; out[base + 2 * K + k] = h;
}
__global__ void transpose_dup2(const float* __restrict__ W, __half* __restrict__ out,
                               int Kd, int Nd) {
    int i = blockIdx.x * 256 + threadIdx.x;
    if (i >= Nd * Kd) return;
    int n = i / Kd, k = i - n * Kd;
    __half h = __float2half_rn(W[(size_t)k * Nd + n]);
    size_t base = (size_t)n * 2 * Kd;
    out[base + k] = h; out[base + Kd + k] = h;
}
__global__ void transpose_single(const float* __restrict__ W, __half* __restrict__ out,
                                 int Kd, int Nd) {
    int i = blockIdx.x * 256 + threadIdx.x;
    if (i >= Nd * Kd) return;
    int n = i / Kd, k = i - n * Kd;
    out[(size_t)n * Kd + k] = __float2half_rn(W[(size_t)k * Nd + n]);
}
__global__ void prep_qkvW(const float* __restrict__ Wq, const float* __restrict__ Wk,
                          const float* __restrict__ Wv) {
    int i = blockIdx.x * 256 + threadIdx.x;
    if (i >= 1536 * DMODEL) return;
    int n = i >> 9, k = i & 511;
    int which = n >> 9, h = (n >> 6) & 7, kk = n & 63;
    const float* W = which == 0 ? Wq : which == 1 ? Wk : Wv;
    __half hh, ll; split2h(W[((size_t)h * DMODEL + k) * HD + kk], hh, ll);
    size_t base = (size_t)n * 1536;
    g_qkvWp[base + k] = hh; g_qkvWp[base + 512 + k] = hh; g_qkvWp[base + 1024 + k] = ll;
}

// ---------------- fp16 K-concat GEMM (proven core) -------------------------
// EPI: 0 = QKV scatter (q/k hi+lo, v single); 1 = pair-store [hi|lo];
//      2 = bias+relu+single store; 3 = bias + fp32 out
constexpr int STAGE_B = 32768;
constexpr int GEMM_SMEM = 3 * STAGE_B;   // 96 KB

template <int EPI>
__global__ __launch_bounds__(256, 2)
void mma_gemm(const __half* __restrict__ A, const __half* __restrict__ B,
              const float* __restrict__ bias, float* __restrict__ outF,
              __half* __restrict__ outB, int N, int Kp) {
    extern __shared__ char smdyn[];
    const uint32_t sb = smem_u32(smdyn);
    const int tid = threadIdx.x, lane = tid & 31, wid = tid >> 5;
    const int wm = wid & 3, wn = wid >> 2;
    const int rowBase = blockIdx.y * 128, colBase = blockIdx.x * 128;
    const int chunks = Kp >> 6;

    float C[2][8][4];
#pragma unroll
    for (int a = 0; a < 2; a++)
#pragma unroll
        for (int b = 0; b < 8; b++)
#pragma unroll
            for (int c = 0; c < 4; c++) C[a][b][c] = 0.f;

    auto issue = [&](int cchunk) {
        int s = cchunk % 3;
        uint32_t stA = sb + s * STAGE_B, stB = stA + 16384;
        const char* Ag = (const char*)(A + (size_t)rowBase * Kp + cchunk * 64);
        const char* Bg = (const char*)(B + (size_t)colBase * Kp + cchunk * 64);
#pragma unroll
        for (int i = 0; i < 4; i++) {
            int id = tid + i * 256;
            int r = id >> 3, ch = id & 7;
            uint32_t off = (uint32_t)(r * 8 + (ch ^ (r & 7))) * 16;
            CP_ASYNC16(stA + off, Ag + (size_t)r * Kp * 2 + ch * 16);
            CP_ASYNC16(stB + off, Bg + (size_t)r * Kp * 2 + ch * 16);
        }
        CP_COMMIT();
    };

    issue(0);
    if (chunks > 1) issue(1);

    const int laneA_row = lane & 15;
    const int laneA_ks  = lane >> 4;
    const int laneB_row = (lane & 7) + ((lane >> 4) << 3);
    const int laneB_ks  = (lane >> 3) & 1;

    for (int c = 0; c < chunks; c++) {
        CP_WAIT(1);
        __syncthreads();
        if (c + 2 < chunks) issue(c + 2);

        uint32_t stA = sb + (c % 3) * STAGE_B, stB = stA + 16384;

#pragma unroll
        for (int ks = 0; ks < 4; ks++) {
            uint32_t a[2][4];
#pragma unroll
            for (int mt = 0; mt < 2; mt++) {
                int rowA = wm * 32 + mt * 16 + laneA_row;
                int chA = ks * 2 + laneA_ks;
                uint32_t ad = stA + (uint32_t)(rowA * 8 + (chA ^ (rowA & 7))) * 16;
                LDSM4(a[mt][0], a[mt][1], a[mt][2], a[mt][3], ad);
            }
#pragma unroll
            for (int np = 0; np < 4; np++) {
                int rowB = wn * 64 + np * 16 + laneB_row;
                int chB = ks * 2 + laneB_ks;
                uint32_t bd = stB + (uint32_t)(rowB * 8 + (chB ^ (rowB & 7))) * 16;
                uint32_t b0, b1, b2, b3;
                LDSM4(b0, b1, b2, b3, bd);
#pragma unroll
                for (int mt = 0; mt < 2; mt++) {
                    MMA16816(C[mt][np * 2 + 0], a[mt], b0, b1);
                    MMA16816(C[mt][np * 2 + 1], a[mt], b2, b3);
                }
            }
        }
    }

#pragma unroll
    for (int mt = 0; mt < 2; mt++) {
#pragma unroll
        for (int half = 0; half < 2; half++) {
            int m = rowBase + wm * 32 + mt * 16 + (lane >> 2) + half * 8;
#pragma unroll
            for (int nt = 0; nt < 8; nt++) {
                int n = colBase + wn * 64 + nt * 8 + (lane & 3) * 2;
                float v0 = C[mt][nt][half * 2 + 0];
                float v1 = C[mt][nt][half * 2 + 1];
                if (EPI == 0) {
                    int b = m >> 11, t = m & 2047;
                    int which = n >> 9, h = (n >> 6) & 7, kk = n & 63;
                    size_t idx = ((size_t)((b * NH + h) * SEQ + t)) * HD + kk;
                    if (which == 2) {
                        *(uint32_t*)&g_vhi[idx] = pack_h(v0, v1);
                    } else {
                        __half* dh = which == 0 ? g_qhi : g_khi;
                        __half* dl = which == 0 ? g_qlo : g_klo;
                        uint32_t hi, lo;
                        pack_hl(v0, v1, hi, lo);
                        *(uint32_t*)&dh[idx] = hi;
                        *(uint32_t*)&dl[idx] = lo;
                    }
                } else if (EPI == 3) {
                    *(float2*)&outF[(size_t)m * N + n] =
                        make_float2(v0 + bias[n], v1 + bias[n + 1]);
                } else if (EPI == 2) {
                    v0 = fmaxf(v0 + bias[n], 0.f);
                    v1 = fmaxf(v1 + bias[n + 1], 0.f);
                    *(uint32_t*)&outB[(size_t)m * N + n] = pack_h(v0, v1);
                } else {
                    uint32_t hi, lo;
                    pack_hl(v0, v1, hi, lo);
                    size_t base = (size_t)m * (2 * N) + n;
                    *(uint32_t*)&outB[base]     = hi;
                    *(uint32_t*)&outB[base + N] = lo;
                }
            }
        }
    }
}

// ---------------- flash attention: S 3-term, O = Ph·Vh (P,V single) --------
constexpr int F_STAGE = 24576;                     // Kh 8K | Kl 8K | Vh 8K
constexpr int FLASH_SMEM = 32768 + 2 * F_STAGE;    // 80 KB

__global__ __launch_bounds__(256, 1)
void flash_mma() {
    extern __shared__ char smdyn[];
    const uint32_t sb = smem_u32(smdyn);
    const int tid = threadIdx.x, lane = tid & 31, wid = tid >> 5;
    const int bh = blockIdx.y;
    const int b = bh >> 3, h = bh & 7;
    const int q0 = blockIdx.x * 128;

    const uint32_t sQh = sb, sQl = sb + 16384;
    const size_t bhBase = (size_t)bh * SEQ * HD;

    auto issue_kv = [&](int t) {
        int s = t & 1;
        uint32_t st = sb + 32768 + s * F_STAGE;
        int key0 = t * 64;
        const __half* srcs[3] = { g_khi, g_klo, g_vhi };
#pragma unroll
        for (int arr = 0; arr < 3; arr++) {
            uint32_t base = st + arr * 8192;
            const char* g = (const char*)(srcs[arr] + bhBase + (size_t)key0 * HD);
#pragma unroll
            for (int i = 0; i < 2; i++) {
                int id = tid + i * 256;
                int r = id >> 3, ch = id & 7;
                uint32_t off = (uint32_t)(r * 8 + (ch ^ (r & 7))) * 16;
                CP_ASYNC16(base + off, g + (size_t)r * 128 + ch * 16);
            }
        }
        CP_COMMIT();
    };

    issue_kv(0);
    issue_kv(1);

#pragma unroll
    for (int i = 0; i < 4; i++) {
        int id = tid + i * 256;
        int r = id >> 3, ch = id & 7;
        uint32_t off = (uint32_t)(r * 8 + (ch ^ (r & 7))) * 16;
        size_t gidx = bhBase + (size_t)(q0 + r) * HD + ch * 8;
        *(float4*)(smdyn + (sQh - sb) + off) = *(const float4*)&g_qhi[gidx];
        *(float4*)(smdyn + (sQl - sb) + off) = *(const float4*)&g_qlo[gidx];
    }
    __syncthreads();

    const int laneA_row = lane & 15;
    const int laneA_ks  = lane >> 4;
    const int laneB_row = (lane & 7) + ((lane >> 4) << 3);
    const int laneB_ks  = (lane >> 3) & 1;
    const int t4 = lane >> 3, rr = lane & 7;

    uint32_t qh[4][4], ql[4][4];
#pragma unroll
    for (int ks = 0; ks < 4; ks++) {
        int rowA = wid * 16 + laneA_row;
        int chA = ks * 2 + laneA_ks;
        uint32_t sw = (uint32_t)(rowA * 8 + (chA ^ (rowA & 7))) * 16;
        LDSM4(qh[ks][0], qh[ks][1], qh[ks][2], qh[ks][3], sQh + sw);
        LDSM4(ql[ks][0], ql[ks][1], ql[ks][2], ql[ks][3], sQl + sw);
    }

    float o[8][4];
#pragma unroll
    for (int nt = 0; nt < 8; nt++)
#pragma unroll
        for (int j = 0; j < 4; j++) o[nt][j] = 0.f;
    float m0 = -1e30f, m1 = -1e30f, l0 = 0.f, l1 = 0.f;

    constexpr int NT = SEQ / 64;
    for (int kt = 0; kt < NT; kt++) {
        if (kt < NT - 1) { CP_WAIT(1); } else { CP_WAIT(0); }
        __syncthreads();

        uint32_t st = sb + 32768 + (kt & 1) * F_STAGE;
        uint32_t sKh = st, sKl = st + 8192, sVh = st + 16384;

        float c[8][4];
#pragma unroll
        for (int nt = 0; nt < 8; nt++)
#pragma unroll
            for (int j = 0; j < 4; j++) c[nt][j] = 0.f;

#pragma unroll
        for (int ks = 0; ks < 4; ks++) {
#pragma unroll
            for (int np = 0; np < 4; np++) {
                int rowB = np * 16 + laneB_row;
                int chB = ks * 2 + laneB_ks;
                uint32_t sw = (uint32_t)(rowB * 8 + (chB ^ (rowB & 7))) * 16;
                uint32_t kh0, kh1, kh2, kh3, kl0, kl1, kl2, kl3;
                LDSM4(kh0, kh1, kh2, kh3, sKh + sw);
                LDSM4(kl0, kl1, kl2, kl3, sKl + sw);
                MMA16816(c[np * 2 + 0], qh[ks], kh0, kh1);
                MMA16816(c[np * 2 + 0], ql[ks], kh0, kh1);
                MMA16816(c[np * 2 + 0], qh[ks], kl0, kl1);
                MMA16816(c[np * 2 + 1], qh[ks], kh2, kh3);
                MMA16816(c[np * 2 + 1], ql[ks], kh2, kh3);
                MMA16816(c[np * 2 + 1], qh[ks], kl2, kl3);
            }
        }

        float mx0 = -1e30f, mx1 = -1e30f;
#pragma unroll
        for (int nt = 0; nt < 8; nt++) {
            c[nt][0] *= 0.125f; c[nt][1] *= 0.125f;
            c[nt][2] *= 0.125f; c[nt][3] *= 0.125f;
            mx0 = fmaxf(mx0, fmaxf(c[nt][0], c[nt][1]));
            mx1 = fmaxf(mx1, fmaxf(c[nt][2], c[nt][3]));
        }
        mx0 = fmaxf(mx0, __shfl_xor_sync(0xffffffffu, mx0, 1));
        mx0 = fmaxf(mx0, __shfl_xor_sync(0xffffffffu, mx0, 2));
        mx1 = fmaxf(mx1, __shfl_xor_sync(0xffffffffu, mx1, 1));
        mx1 = fmaxf(mx1, __shfl_xor_sync(0xffffffffu, mx1, 2));

        float mn0 = fmaxf(m0, mx0), mn1 = fmaxf(m1, mx1);
        float a0 = __expf(m0 - mn0), a1 = __expf(m1 - mn1);
        m0 = mn0; m1 = mn1;

        float s0 = 0.f, s1 = 0.f;
#pragma unroll
        for (int nt = 0; nt < 8; nt++) {
            c[nt][0] = __expf(c[nt][0] - m0);
            c[nt][1] = __expf(c[nt][1] - m0);
            c[nt][2] = __expf(c[nt][2] - m1);
            c[nt][3] = __expf(c[nt][3] - m1);
            s0 += c[nt][0] + c[nt][1];
            s1 += c[nt][2] + c[nt][3];
        }
        s0 += __shfl_xor_sync(0xffffffffu, s0, 1);
        s0 += __shfl_xor_sync(0xffffffffu, s0, 2);
        s1 += __shfl_xor_sync(0xffffffffu, s1, 1);
        s1 += __shfl_xor_sync(0xffffffffu, s1, 2);
        l0 = l0 * a0 + s0;
        l1 = l1 * a1 + s1;

#pragma unroll
        for (int nt = 0; nt < 8; nt++) {
            o[nt][0] *= a0; o[nt][1] *= a0;
            o[nt][2] *= a1; o[nt][3] *= a1;
        }

        // P -> single fp16 A-fragments
        uint32_t ph[4][4];
#pragma unroll
        for (int pk = 0; pk < 4; pk++) {
            int n0i = pk * 2, n1i = pk * 2 + 1;
            ph[pk][0] = pack_h(c[n0i][0], c[n0i][1]);
            ph[pk][1] = pack_h(c[n0i][2], c[n0i][3]);
            ph[pk][2] = pack_h(c[n1i][0], c[n1i][1]);
            ph[pk][3] = pack_h(c[n1i][2], c[n1i][3]);
        }

        // O += Ph·Vh
#pragma unroll
        for (int pk = 0; pk < 4; pk++) {
#pragma unroll
            for (int np = 0; np < 4; np++) {
                int rowV = pk * 16 + (t4 & 1) * 8 + rr;
                int chV = np * 2 + (t4 >> 1);
                uint32_t sw = (uint32_t)(rowV * 8 + (chV ^ (rowV & 7))) * 16;
                uint32_t vh0, vh1, vh2, vh3;
                LDSM4T(vh0, vh1, vh2, vh3, sVh + sw);
                MMA16816(o[np * 2 + 0], ph[pk], vh0, vh1);
                MMA16816(o[np * 2 + 1], ph[pk], vh2, vh3);
            }
        }

        __syncthreads();
        if (kt + 2 < NT) issue_kv(kt + 2);
    }

    // epilogue: att' PAIR [hi|lo], raw-reshape rows of length 1024
    float inv0 = 1.f / l0, inv1 = 1.f / l1;
#pragma unroll
    for (int half = 0; half < 2; half++) {
        int t = q0 + wid * 16 + (lane >> 2) + half * 8;
        float inv = half ? inv1 : inv0;
        size_t row2 = (size_t)b * SEQ + h * 256 + (t >> 3);
        size_t rb = row2 * 1024 + (t & 7) * 64;
#pragma unroll
        for (int nt = 0; nt < 8; nt++) {
            int col = nt * 8 + (lane & 3) * 2;
            float v0 = o[nt][half * 2 + 0] * inv;
            float v1 = o[nt][half * 2 + 1] * inv;
            uint32_t hi, lo;
            pack_hl(v0, v1, hi, lo);
            *(uint32_t*)&g_attp[rb + col]       = hi;
            *(uint32_t*)&g_attp[rb + 512 + col] = lo;
        }
    }
}

// ---------------- launch ----------------
extern "C" void kernel_launch(void* const* d_in, const int* in_sizes, int n_in,
                              void* d_out, int out_size) {
    const float* x  = (const float*)d_in[0];
    const float* Wq = (const float*)d_in[1];
    const float* Wk = (const float*)d_in[2];
    const float* Wv = (const float*)d_in[3];
    const float* Wo = (const float*)d_in[4];
    const float* W1 = (const float*)d_in[5];
    const float* b1 = (const float*)d_in[6];
    const float* W2 = (const float*)d_in[7];
    const float* b2 = (const float*)d_in[8];
    float* y = (float*)d_out;

    void *xp, *qwp, *wop, *w1p, *w2p, *atp, *outp, *hp;
    cudaGetSymbolAddress(&xp,  g_xp);
    cudaGetSymbolAddress(&qwp, g_qkvWp);
    cudaGetSymbolAddress(&wop, g_WoTp);
    cudaGetSymbolAddress(&w1p, g_W1Tp);
    cudaGetSymbolAddress(&w2p, g_W2Tp);
    cudaGetSymbolAddress(&atp, g_attp);
    cudaGetSymbolAddress(&outp, g_outp);
    cudaGetSymbolAddress(&hp,  g_h16);

    cudaFuncSetAttribute(mma_gemm<0>, cudaFuncAttributeMaxDynamicSharedMemorySize, GEMM_SMEM);
    cudaFuncSetAttribute(mma_gemm<1>, cudaFuncAttributeMaxDynamicSharedMemorySize, GEMM_SMEM);
    cudaFuncSetAttribute(mma_gemm<2>, cudaFuncAttributeMaxDynamicSharedMemorySize, GEMM_SMEM);
    cudaFuncSetAttribute(mma_gemm<3>, cudaFuncAttributeMaxDynamicSharedMemorySize, GEMM_SMEM);
    cudaFuncSetAttribute(flash_mma, cudaFuncAttributeMaxDynamicSharedMemorySize, FLASH_SMEM);

    // prep
    split3_rows<<<(MROWS * DMODEL + 255) / 256, 256>>>(x, (__half*)xp, MROWS, DMODEL);
    prep_qkvW<<<(1536 * DMODEL + 255) / 256, 256>>>(Wq, Wk, Wv);
    transpose_dup2<<<(DMODEL * DMODEL + 255) / 256, 256>>>(Wo, (__half*)wop, DMODEL, DMODEL);
    transpose_dup2<<<(DMODEL * FFI + 255) / 256, 256>>>(W1, (__half*)w1p, DMODEL, FFI);
    transpose_single<<<(FFI * DMODEL + 255) / 256, 256>>>(W2, (__half*)w2p, FFI, DMODEL);

    // 1. QKV (3-term, Kp=1536) -> q/k hi+lo, v single
    mma_gemm<0><<<dim3(12, 64), 256, GEMM_SMEM>>>(
        (const __half*)xp, (const __half*)qwp, nullptr, nullptr, nullptr, 1536, 1536);

    // 2. flash attention (P,V single) -> att' pair [hi|lo]
    flash_mma<<<dim3(SEQ / 128, BH), 256, FLASH_SMEM>>>();

    // 3. Wo (2-term, Kp=1024) -> out' pair [hi|lo]
    mma_gemm<1><<<dim3(4, 64), 256, GEMM_SMEM>>>(
        (const __half*)atp, (const __half*)wop, nullptr, nullptr,
        (__half*)outp, DMODEL, 1024);

    // 4. FFN1 (2-term, Kp=1024, bias+relu) -> h single fp16
    mma_gemm<2><<<dim3(16, 64), 256, GEMM_SMEM>>>(
        (const __half*)outp, (const __half*)w1p, b1, nullptr,
        (__half*)hp, FFI, 1024);

    // 5. FFN2 (plain, Kp=2048, bias) -> y fp32
    mma_gemm<3><<<dim3(4, 64), 256, GEMM_SMEM>>>(
        (const __half*)hp, (const __half*)w2p, b2, y, nullptr, DMODEL, 2048);
}

// round 16
// speedup vs baseline: 1.7058x; 1.0301x over previous
#include <cuda_runtime.h>
#include <cuda_fp16.h>
#include <math.h>
#include <stdint.h>

constexpr int BATCH  = 4;
constexpr int SEQ    = 2048;
constexpr int DMODEL = 512;
constexpr int NH     = 8;
constexpr int HD     = 64;
constexpr int FFI    = 2048;
constexpr int MROWS  = BATCH * SEQ;   // 8192
constexpr int BH     = BATCH * NH;    // 32

// ---------------- baseline-PTX helpers ----------------
__device__ __forceinline__ uint32_t smem_u32(const void* p) {
    uint32_t a;
    asm("{ .reg .u64 t; cvta.to.shared.u64 t, %1; cvt.u32.u64 %0, t; }" : "=r"(a) : "l"(p));
    return a;
}
#define CP_ASYNC16(dst, src) \
    asm volatile("cp.async.cg.shared.global [%0], [%1], 16;" :: "r"(dst), "l"(src))
#define CP_COMMIT() asm volatile("cp.async.commit_group;" ::: "memory")
#define CP_WAIT(n)  asm volatile("cp.async.wait_group %0;" :: "n"(n) : "memory")
#define LDSM4(r0, r1, r2, r3, addr) \
    asm volatile("ldmatrix.sync.aligned.m8n8.x4.shared.b16 {%0,%1,%2,%3}, [%4];" \
        : "=r"(r0), "=r"(r1), "=r"(r2), "=r"(r3) : "r"(addr))
#define LDSM4T(r0, r1, r2, r3, addr) \
    asm volatile("ldmatrix.sync.aligned.m8n8.x4.trans.shared.b16 {%0,%1,%2,%3}, [%4];" \
        : "=r"(r0), "=r"(r1), "=r"(r2), "=r"(r3) : "r"(addr))
#define MMA16816(c, a, b0, b1) \
    asm volatile("mma.sync.aligned.m16n8k16.row.col.f32.f16.f16.f32 " \
        "{%0,%1,%2,%3}, {%4,%5,%6,%7}, {%8,%9}, {%0,%1,%2,%3};" \
        : "+f"((c)[0]), "+f"((c)[1]), "+f"((c)[2]), "+f"((c)[3]) \
        : "r"((a)[0]), "r"((a)[1]), "r"((a)[2]), "r"((a)[3]), "r"(b0), "r"(b1))

__device__ __forceinline__ void split2h(float v, __half& h, __half& l) {
    h = __float2half_rn(v);
    l = __float2half_rn(v - __half2float(h));
}
__device__ __forceinline__ uint32_t pack_h(float x, float y) {
    union { __half2 h2; uint32_t u; } r;
    r.h2 = __halves2half2(__float2half_rn(x), __float2half_rn(y));
    return r.u;
}
__device__ __forceinline__ void pack_hl(float x, float y, uint32_t& hi, uint32_t& lo) {
    __half hx, lx, hy, ly;
    split2h(x, hx, lx);
    split2h(y, hy, ly);
    union { __half2 h2; uint32_t u; } a, b;
    a.h2 = __halves2half2(hx, hy);
    b.h2 = __halves2half2(lx, ly);
    hi = a.u; lo = b.u;
}

// ---------------- device scratch ----------------
// QKV: 3-term A'=[hi|lo|hi], B'=[hi|hi|lo]; q/k hi+lo, v single
// Wo:  plain (att single, fp16(Wo) single, Kp=512)
// FFN1: 2-term A'=out pair (exact), B'=[W1|W1] dup -> h single
// FFN2: plain (h single, W2 single, Kp=2048)
#define AL __align__(16)
__device__ AL __half g_xp[MROWS * 3 * DMODEL];            // x'    [8192,1536]
__device__ AL __half g_qkvWp[1536 * 3 * DMODEL];          // B'qkv [1536,1536]
__device__ AL __half g_WoTp[DMODEL * DMODEL];             // Wo^T  [512,512] single
__device__ AL __half g_W1Tp[FFI * 2 * DMODEL];            // B'W1  [2048,1024] dup
__device__ AL __half g_W2Tp[DMODEL * FFI];                // W2^T  [512,2048] single
__device__ AL __half g_qhi[BH * SEQ * HD], g_qlo[BH * SEQ * HD];
__device__ AL __half g_khi[BH * SEQ * HD], g_klo[BH * SEQ * HD];
__device__ AL __half g_vhi[BH * SEQ * HD];                // v single
__device__ AL __half g_att16[MROWS * DMODEL];             // att   [8192,512] single
__device__ AL __half g_outp[MROWS * 2 * DMODEL];          // out'  [8192,1024] pair
__device__ AL __half g_h16[MROWS * FFI];                  // h     [8192,2048] single

// ---------------- prep kernels ----------------
__global__ void split3_rows(const float* __restrict__ in, __half* __restrict__ out,
                            int M, int K) {
    int i = blockIdx.x * 256 + threadIdx.x;
    if (i >= M * K) return;
    int m = i / K, k = i - m * K;
    __half h, l; split2h(in[i], h, l);
    size_t base = (size_t)m * 3 * K;
    out[base + k] = h; out[base + K + k] = l; out[base + 2 * K + k] = h;
}
__global__ void transpose_dup2(const float* __restrict__ W, __half* __restrict__ out,
                               int Kd, int Nd) {
    int i = blockIdx.x * 256 + threadIdx.x;
    if (i >= Nd * Kd) return;
    int n = i / Kd, k = i - n * Kd;
    __half h = __float2half_rn(W[(size_t)k * Nd + n]);
    size_t base = (size_t)n * 2 * Kd;
    out[base + k] = h; out[base + Kd + k] = h;
}
__global__ void transpose_single(const float* __restrict__ W, __half* __restrict__ out,
                                 int Kd, int Nd) {
    int i = blockIdx.x * 256 + threadIdx.x;
    if (i >= Nd * Kd) return;
    int n = i / Kd, k = i - n * Kd;
    out[(size_t)n * Kd + k] = __float2half_rn(W[(size_t)k * Nd + n]);
}
__global__ void prep_qkvW(const float* __restrict__ Wq, const float* __restrict__ Wk,
                          const float* __restrict__ Wv) {
    int i = blockIdx.x * 256 + threadIdx.x;
    if (i >= 1536 * DMODEL) return;
    int n = i >> 9, k = i & 511;
    int which = n >> 9, h = (n >> 6) & 7, kk = n & 63;
    const float* W = which == 0 ? Wq : which == 1 ? Wk : Wv;
    __half hh, ll; split2h(W[((size_t)h * DMODEL + k) * HD + kk], hh, ll);
    size_t base = (size_t)n * 1536;
    g_qkvWp[base + k] = hh; g_qkvWp[base + 512 + k] = hh; g_qkvWp[base + 1024 + k] = ll;
}

// ---------------- fp16 K-concat GEMM (proven core) -------------------------
// EPI: 0 = QKV scatter (q/k hi+lo, v single); 1 = pair-store [hi|lo];
//      2 = bias+relu+single store; 3 = bias + fp32 out
constexpr int STAGE_B = 32768;
constexpr int GEMM_SMEM = 3 * STAGE_B;   // 96 KB

template <int EPI>
__global__ __launch_bounds__(256, 2)
void mma_gemm(const __half* __restrict__ A, const __half* __restrict__ B,
              const float* __restrict__ bias, float* __restrict__ outF,
              __half* __restrict__ outB, int N, int Kp) {
    extern __shared__ char smdyn[];
    const uint32_t sb = smem_u32(smdyn);
    const int tid = threadIdx.x, lane = tid & 31, wid = tid >> 5;
    const int wm = wid & 3, wn = wid >> 2;
    const int rowBase = blockIdx.y * 128, colBase = blockIdx.x * 128;
    const int chunks = Kp >> 6;

    float C[2][8][4];
#pragma unroll
    for (int a = 0; a < 2; a++)
#pragma unroll
        for (int b = 0; b < 8; b++)
#pragma unroll
            for (int c = 0; c < 4; c++) C[a][b][c] = 0.f;

    auto issue = [&](int cchunk) {
        int s = cchunk % 3;
        uint32_t stA = sb + s * STAGE_B, stB = stA + 16384;
        const char* Ag = (const char*)(A + (size_t)rowBase * Kp + cchunk * 64);
        const char* Bg = (const char*)(B + (size_t)colBase * Kp + cchunk * 64);
#pragma unroll
        for (int i = 0; i < 4; i++) {
            int id = tid + i * 256;
            int r = id >> 3, ch = id & 7;
            uint32_t off = (uint32_t)(r * 8 + (ch ^ (r & 7))) * 16;
            CP_ASYNC16(stA + off, Ag + (size_t)r * Kp * 2 + ch * 16);
            CP_ASYNC16(stB + off, Bg + (size_t)r * Kp * 2 + ch * 16);
        }
        CP_COMMIT();
    };

    issue(0);
    if (chunks > 1) issue(1);

    const int laneA_row = lane & 15;
    const int laneA_ks  = lane >> 4;
    const int laneB_row = (lane & 7) + ((lane >> 4) << 3);
    const int laneB_ks  = (lane >> 3) & 1;

    for (int c = 0; c < chunks; c++) {
        CP_WAIT(1);
        __syncthreads();
        if (c + 2 < chunks) issue(c + 2);

        uint32_t stA = sb + (c % 3) * STAGE_B, stB = stA + 16384;

#pragma unroll
        for (int ks = 0; ks < 4; ks++) {
            uint32_t a[2][4];
#pragma unroll
            for (int mt = 0; mt < 2; mt++) {
                int rowA = wm * 32 + mt * 16 + laneA_row;
                int chA = ks * 2 + laneA_ks;
                uint32_t ad = stA + (uint32_t)(rowA * 8 + (chA ^ (rowA & 7))) * 16;
                LDSM4(a[mt][0], a[mt][1], a[mt][2], a[mt][3], ad);
            }
#pragma unroll
            for (int np = 0; np < 4; np++) {
                int rowB = wn * 64 + np * 16 + laneB_row;
                int chB = ks * 2 + laneB_ks;
                uint32_t bd = stB + (uint32_t)(rowB * 8 + (chB ^ (rowB & 7))) * 16;
                uint32_t b0, b1, b2, b3;
                LDSM4(b0, b1, b2, b3, bd);
#pragma unroll
                for (int mt = 0; mt < 2; mt++) {
                    MMA16816(C[mt][np * 2 + 0], a[mt], b0, b1);
                    MMA16816(C[mt][np * 2 + 1], a[mt], b2, b3);
                }
            }
        }
    }

#pragma unroll
    for (int mt = 0; mt < 2; mt++) {
#pragma unroll
        for (int half = 0; half < 2; half++) {
            int m = rowBase + wm * 32 + mt * 16 + (lane >> 2) + half * 8;
#pragma unroll
            for (int nt = 0; nt < 8; nt++) {
                int n = colBase + wn * 64 + nt * 8 + (lane & 3) * 2;
                float v0 = C[mt][nt][half * 2 + 0];
                float v1 = C[mt][nt][half * 2 + 1];
                if (EPI == 0) {
                    int b = m >> 11, t = m & 2047;
                    int which = n >> 9, h = (n >> 6) & 7, kk = n & 63;
                    size_t idx = ((size_t)((b * NH + h) * SEQ + t)) * HD + kk;
                    if (which == 2) {
                        *(uint32_t*)&g_vhi[idx] = pack_h(v0, v1);
                    } else {
                        __half* dh = which == 0 ? g_qhi : g_khi;
                        __half* dl = which == 0 ? g_qlo : g_klo;
                        uint32_t hi, lo;
                        pack_hl(v0, v1, hi, lo);
                        *(uint32_t*)&dh[idx] = hi;
                        *(uint32_t*)&dl[idx] = lo;
                    }
                } else if (EPI == 3) {
                    *(float2*)&outF[(size_t)m * N + n] =
                        make_float2(v0 + bias[n], v1 + bias[n + 1]);
                } else if (EPI == 2) {
                    v0 = fmaxf(v0 + bias[n], 0.f);
                    v1 = fmaxf(v1 + bias[n + 1], 0.f);
                    *(uint32_t*)&outB[(size_t)m * N + n] = pack_h(v0, v1);
                } else {
                    uint32_t hi, lo;
                    pack_hl(v0, v1, hi, lo);
                    size_t base = (size_t)m * (2 * N) + n;
                    *(uint32_t*)&outB[base]     = hi;
                    *(uint32_t*)&outB[base + N] = lo;
                }
            }
        }
    }
}

// ---------------- flash attention: S 3-term, O = Ph·Vh -> att single -------
constexpr int F_STAGE = 24576;                     // Kh 8K | Kl 8K | Vh 8K
constexpr int FLASH_SMEM = 32768 + 2 * F_STAGE;    // 80 KB

__global__ __launch_bounds__(256, 1)
void flash_mma() {
    extern __shared__ char smdyn[];
    const uint32_t sb = smem_u32(smdyn);
    const int tid = threadIdx.x, lane = tid & 31, wid = tid >> 5;
    const int bh = blockIdx.y;
    const int b = bh >> 3, h = bh & 7;
    const int q0 = blockIdx.x * 128;

    const uint32_t sQh = sb, sQl = sb + 16384;
    const size_t bhBase = (size_t)bh * SEQ * HD;

    auto issue_kv = [&](int t) {
        int s = t & 1;
        uint32_t st = sb + 32768 + s * F_STAGE;
        int key0 = t * 64;
        const __half* srcs[3] = { g_khi, g_klo, g_vhi };
#pragma unroll
        for (int arr = 0; arr < 3; arr++) {
            uint32_t base = st + arr * 8192;
            const char* g = (const char*)(srcs[arr] + bhBase + (size_t)key0 * HD);
#pragma unroll
            for (int i = 0; i < 2; i++) {
                int id = tid + i * 256;
                int r = id >> 3, ch = id & 7;
                uint32_t off = (uint32_t)(r * 8 + (ch ^ (r & 7))) * 16;
                CP_ASYNC16(base + off, g + (size_t)r * 128 + ch * 16);
            }
        }
        CP_COMMIT();
    };

    issue_kv(0);
    issue_kv(1);

#pragma unroll
    for (int i = 0; i < 4; i++) {
        int id = tid + i * 256;
        int r = id >> 3, ch = id & 7;
        uint32_t off = (uint32_t)(r * 8 + (ch ^ (r & 7))) * 16;
        size_t gidx = bhBase + (size_t)(q0 + r) * HD + ch * 8;
        *(float4*)(smdyn + (sQh - sb) + off) = *(const float4*)&g_qhi[gidx];
        *(float4*)(smdyn + (sQl - sb) + off) = *(const float4*)&g_qlo[gidx];
    }
    __syncthreads();

    const int laneA_row = lane & 15;
    const int laneA_ks  = lane >> 4;
    const int laneB_row = (lane & 7) + ((lane >> 4) << 3);
    const int laneB_ks  = (lane >> 3) & 1;
    const int t4 = lane >> 3, rr = lane & 7;

    uint32_t qh[4][4], ql[4][4];
#pragma unroll
    for (int ks = 0; ks < 4; ks++) {
        int rowA = wid * 16 + laneA_row;
        int chA = ks * 2 + laneA_ks;
        uint32_t sw = (uint32_t)(rowA * 8 + (chA ^ (rowA & 7))) * 16;
        LDSM4(qh[ks][0], qh[ks][1], qh[ks][2], qh[ks][3], sQh + sw);
        LDSM4(ql[ks][0], ql[ks][1], ql[ks][2], ql[ks][3], sQl + sw);
    }

    float o[8][4];
#pragma unroll
    for (int nt = 0; nt < 8; nt++)
#pragma unroll
        for (int j = 0; j < 4; j++) o[nt][j] = 0.f;
    float m0 = -1e30f, m1 = -1e30f, l0 = 0.f, l1 = 0.f;

    constexpr int NT = SEQ / 64;
    for (int kt = 0; kt < NT; kt++) {
        if (kt < NT - 1) { CP_WAIT(1); } else { CP_WAIT(0); }
        __syncthreads();

        uint32_t st = sb + 32768 + (kt & 1) * F_STAGE;
        uint32_t sKh = st, sKl = st + 8192, sVh = st + 16384;

        float c[8][4];
#pragma unroll
        for (int nt = 0; nt < 8; nt++)
#pragma unroll
            for (int j = 0; j < 4; j++) c[nt][j] = 0.f;

#pragma unroll
        for (int ks = 0; ks < 4; ks++) {
#pragma unroll
            for (int np = 0; np < 4; np++) {
                int rowB = np * 16 + laneB_row;
                int chB = ks * 2 + laneB_ks;
                uint32_t sw = (uint32_t)(rowB * 8 + (chB ^ (rowB & 7))) * 16;
                uint32_t kh0, kh1, kh2, kh3, kl0, kl1, kl2, kl3;
                LDSM4(kh0, kh1, kh2, kh3, sKh + sw);
                LDSM4(kl0, kl1, kl2, kl3, sKl + sw);
                MMA16816(c[np * 2 + 0], qh[ks], kh0, kh1);
                MMA16816(c[np * 2 + 0], ql[ks], kh0, kh1);
                MMA16816(c[np * 2 + 0], qh[ks], kl0, kl1);
                MMA16816(c[np * 2 + 1], qh[ks], kh2, kh3);
                MMA16816(c[np * 2 + 1], ql[ks], kh2, kh3);
                MMA16816(c[np * 2 + 1], qh[ks], kl2, kl3);
            }
        }

        float mx0 = -1e30f, mx1 = -1e30f;
#pragma unroll
        for (int nt = 0; nt < 8; nt++) {
            c[nt][0] *= 0.125f; c[nt][1] *= 0.125f;
            c[nt][2] *= 0.125f; c[nt][3] *= 0.125f;
            mx0 = fmaxf(mx0, fmaxf(c[nt][0], c[nt][1]));
            mx1 = fmaxf(mx1, fmaxf(c[nt][2], c[nt][3]));
        }
        mx0 = fmaxf(mx0, __shfl_xor_sync(0xffffffffu, mx0, 1));
        mx0 = fmaxf(mx0, __shfl_xor_sync(0xffffffffu, mx0, 2));
        mx1 = fmaxf(mx1, __shfl_xor_sync(0xffffffffu, mx1, 1));
        mx1 = fmaxf(mx1, __shfl_xor_sync(0xffffffffu, mx1, 2));

        float mn0 = fmaxf(m0, mx0), mn1 = fmaxf(m1, mx1);
        float a0 = __expf(m0 - mn0), a1 = __expf(m1 - mn1);
        m0 = mn0; m1 = mn1;

        float s0 = 0.f, s1 = 0.f;
#pragma unroll
        for (int nt = 0; nt < 8; nt++) {
            c[nt][0] = __expf(c[nt][0] - m0);
            c[nt][1] = __expf(c[nt][1] - m0);
            c[nt][2] = __expf(c[nt][2] - m1);
            c[nt][3] = __expf(c[nt][3] - m1);
            s0 += c[nt][0] + c[nt][1];
            s1 += c[nt][2] + c[nt][3];
        }
        s0 += __shfl_xor_sync(0xffffffffu, s0, 1);
        s0 += __shfl_xor_sync(0xffffffffu, s0, 2);
        s1 += __shfl_xor_sync(0xffffffffu, s1, 1);
        s1 += __shfl_xor_sync(0xffffffffu, s1, 2);
        l0 = l0 * a0 + s0;
        l1 = l1 * a1 + s1;

#pragma unroll
        for (int nt = 0; nt < 8; nt++) {
            o[nt][0] *= a0; o[nt][1] *= a0;
            o[nt][2] *= a1; o[nt][3] *= a1;
        }

        uint32_t ph[4][4];
#pragma unroll
        for (int pk = 0; pk < 4; pk++) {
            int n0i = pk * 2, n1i = pk * 2 + 1;
            ph[pk][0] = pack_h(c[n0i][0], c[n0i][1]);
            ph[pk][1] = pack_h(c[n0i][2], c[n0i][3]);
            ph[pk][2] = pack_h(c[n1i][0], c[n1i][1]);
            ph[pk][3] = pack_h(c[n1i][2], c[n1i][3]);
        }

#pragma unroll
        for (int pk = 0; pk < 4; pk++) {
#pragma unroll
            for (int np = 0; np < 4; np++) {
                int rowV = pk * 16 + (t4 & 1) * 8 + rr;
                int chV = np * 2 + (t4 >> 1);
                uint32_t sw = (uint32_t)(rowV * 8 + (chV ^ (rowV & 7))) * 16;
                uint32_t vh0, vh1, vh2, vh3;
                LDSM4T(vh0, vh1, vh2, vh3, sVh + sw);
                MMA16816(o[np * 2 + 0], ph[pk], vh0, vh1);
                MMA16816(o[np * 2 + 1], ph[pk], vh2, vh3);
            }
        }

        __syncthreads();
        if (kt + 2 < NT) issue_kv(kt + 2);
    }

    // epilogue: att SINGLE fp16, raw-reshape rows of length 512
    float inv0 = 1.f / l0, inv1 = 1.f / l1;
#pragma unroll
    for (int half = 0; half < 2; half++) {
        int t = q0 + wid * 16 + (lane >> 2) + half * 8;
        float inv = half ? inv1 : inv0;
        size_t row2 = (size_t)b * SEQ + h * 256 + (t >> 3);
        size_t rb = row2 * DMODEL + (t & 7) * 64;
#pragma unroll
        for (int nt = 0; nt < 8; nt++) {
            int col = nt * 8 + (lane & 3) * 2;
            float v0 = o[nt][half * 2 + 0] * inv;
            float v1 = o[nt][half * 2 + 1] * inv;
            *(uint32_t*)&g_att16[rb + col] = pack_h(v0, v1);
        }
    }
}

// ---------------- launch ----------------
extern "C" void kernel_launch(void* const* d_in, const int* in_sizes, int n_in,
                              void* d_out, int out_size) {
    const float* x  = (const float*)d_in[0];
    const float* Wq = (const float*)d_in[1];
    const float* Wk = (const float*)d_in[2];
    const float* Wv = (const float*)d_in[3];
    const float* Wo = (const float*)d_in[4];
    const float* W1 = (const float*)d_in[5];
    const float* b1 = (const float*)d_in[6];
    const float* W2 = (const float*)d_in[7];
    const float* b2 = (const float*)d_in[8];
    float* y = (float*)d_out;

    void *xp, *qwp, *wop, *w1p, *w2p, *atp, *outp, *hp;
    cudaGetSymbolAddress(&xp,  g_xp);
    cudaGetSymbolAddress(&qwp, g_qkvWp);
    cudaGetSymbolAddress(&wop, g_WoTp);
    cudaGetSymbolAddress(&w1p, g_W1Tp);
    cudaGetSymbolAddress(&w2p, g_W2Tp);
    cudaGetSymbolAddress(&atp, g_att16);
    cudaGetSymbolAddress(&outp, g_outp);
    cudaGetSymbolAddress(&hp,  g_h16);

    cudaFuncSetAttribute(mma_gemm<0>, cudaFuncAttributeMaxDynamicSharedMemorySize, GEMM_SMEM);
    cudaFuncSetAttribute(mma_gemm<1>, cudaFuncAttributeMaxDynamicSharedMemorySize, GEMM_SMEM);
    cudaFuncSetAttribute(mma_gemm<2>, cudaFuncAttributeMaxDynamicSharedMemorySize, GEMM_SMEM);
    cudaFuncSetAttribute(mma_gemm<3>, cudaFuncAttributeMaxDynamicSharedMemorySize, GEMM_SMEM);
    cudaFuncSetAttribute(flash_mma, cudaFuncAttributeMaxDynamicSharedMemorySize, FLASH_SMEM);

    // prep
    split3_rows<<<(MROWS * DMODEL + 255) / 256, 256>>>(x, (__half*)xp, MROWS, DMODEL);
    prep_qkvW<<<(1536 * DMODEL + 255) / 256, 256>>>(Wq, Wk, Wv);
    transpose_single<<<(DMODEL * DMODEL + 255) / 256, 256>>>(Wo, (__half*)wop, DMODEL, DMODEL);
    transpose_dup2<<<(DMODEL * FFI + 255) / 256, 256>>>(W1, (__half*)w1p, DMODEL, FFI);
    transpose_single<<<(FFI * DMODEL + 255) / 256, 256>>>(W2, (__half*)w2p, FFI, DMODEL);

    // 1. QKV (3-term, Kp=1536) -> q/k hi+lo, v single
    mma_gemm<0><<<dim3(12, 64), 256, GEMM_SMEM>>>(
        (const __half*)xp, (const __half*)qwp, nullptr, nullptr, nullptr, 1536, 1536);

    // 2. flash attention -> att single fp16
    flash_mma<<<dim3(SEQ / 128, BH), 256, FLASH_SMEM>>>();

    // 3. Wo (plain, Kp=512) -> out' pair [hi|lo]
    mma_gemm<1><<<dim3(4, 64), 256, GEMM_SMEM>>>(
        (const __half*)atp, (const __half*)wop, nullptr, nullptr,
        (__half*)outp, DMODEL, 512);

    // 4. FFN1 (2-term, Kp=1024, bias+relu) -> h single fp16
    mma_gemm<2><<<dim3(16, 64), 256, GEMM_SMEM>>>(
        (const __half*)outp, (const __half*)w1p, b1, nullptr,
        (__half*)hp, FFI, 1024);

    // 5. FFN2 (plain, Kp=2048, bias) -> y fp32
    mma_gemm<3><<<dim3(4, 64), 256, GEMM_SMEM>>>(
        (const __half*)hp, (const __half*)w2p, b2, y, nullptr, DMODEL, 2048);
}